// round 15
// baseline (speedup 1.0000x reference)
#include <cuda_runtime.h>
#include <cstdint>

#define DEVINL static __device__ __forceinline__

// ---------------- problem constants ----------------
constexpr int Bb = 16, Ll = 1024, Dk = 512, Tt = 32, FT = 128;
constexpr int KCH = 16;                        // K chunks of 32
constexpr int TMR = 96;                        // CTA tile rows
constexpr int MT96 = 44;                       // 4224 / 96
constexpr int NT = 128;
constexpr int A_CH = 3072;                     // floats per (tile96, chunk): 4ks*6j*32lane*4
constexpr int B_CHUNK = 4096;                  // floats per (nt, chunk)
constexpr int NSTEP = KCH * 4;                 // 64 K-steps of 8
constexpr int NTILES = MT96 * NT;              // 5632
constexpr int GRID_X = 148 * 39;               // 5772

// fragment-ordered TF32 scratch (+2 chunk pad so tail prefetch stays in-bounds)
__device__ float g_A[(size_t)(MT96 * KCH + 2) * A_CH];    // ~8.7 MB
__device__ float g_B[(size_t)(NT * KCH + 2) * B_CHUNK];   // ~33.6 MB

DEVINL uint32_t f2tf32(float f) {
    uint32_t r;
    asm("cvt.rna.tf32.f32 %0, %1;" : "=r"(r) : "f"(f));
    return r;
}

DEVINL void mma_tf32(float* d, const uint32_t* a, const uint32_t* b) {
    asm volatile(
        "mma.sync.aligned.m16n8k8.row.col.f32.tf32.tf32.f32 "
        "{%0,%1,%2,%3}, {%4,%5,%6,%7}, {%8,%9}, {%0,%1,%2,%3};"
        : "+f"(d[0]), "+f"(d[1]), "+f"(d[2]), "+f"(d[3])
        : "r"(a[0]), "r"(a[1]), "r"(a[2]), "r"(a[3]), "r"(b[0]), "r"(b[1]));
}

// ---------------- merged pre-pass ----------------
// A (flat filter rows f = tile*96 + j*16 + {g, g+8}):
//   inner = ((ks*6 + j)*32 + lane)*4 + r
// B inner = (((ks*2+wn)*4+p)*32 + lane)*4 + q   (R11 layout, unchanged)
__global__ void prep_AB(const float* __restrict__ topic_w,
                        const float* __restrict__ shared_w,
                        const float* __restrict__ emb) {
    const int bx = blockIdx.x, c = blockIdx.y;
    const int tid = threadIdx.x;
    if (bx < MT96) {
        const int tile = bx;
        float* dst = g_A + (size_t)(tile * KCH + c) * A_CH;
        #pragma unroll
        for (int i = 0; i < 3; ++i) {
            const int idx = tid + 256 * i;            // 0..767
            const int lane = idx & 31;
            const int jj = (idx >> 5) % 6;
            const int ks = idx / 192;                 // 0..3
            const int g = lane >> 2, t4 = lane & 3;
            const int f = tile * 96 + jj * 16 + g;    // flat filter row
            const float* r0 = (f < 4096) ? topic_w + (size_t)f * Dk
                                         : shared_w + (size_t)(f - 4096) * Dk;
            const float* r1 = (f + 8 < 4096) ? topic_w + (size_t)(f + 8) * Dk
                                             : shared_w + (size_t)(f + 8 - 4096) * Dk;
            const int k0 = c * 32 + ks * 8 + t4;
            uint4 u = make_uint4(f2tf32(r0[k0]), f2tf32(r1[k0]),
                                 f2tf32(r0[k0 + 4]), f2tf32(r1[k0 + 4]));
            *reinterpret_cast<uint4*>(dst + (size_t)idx * 4) = u;
        }
    } else {
        const int nt = bx - MT96;
        float* dst = g_B + (size_t)(nt * KCH + c) * B_CHUNK;
        #pragma unroll
        for (int i = 0; i < 4; ++i) {
            const int chunk = tid + 256 * i;          // 0..1023
            const int lane = chunk & 31;
            const int p = (chunk >> 5) & 3;
            const int wn = (chunk >> 7) & 1;
            const int ks = chunk >> 8;                // 0..3
            const int g = lane >> 2, t4 = lane & 3;
            const int n0 = nt * 128 + wn * 64 + (2 * p) * 8 + g;
            const int k0 = c * 32 + ks * 8 + t4;
            uint4 u = make_uint4(f2tf32(emb[(size_t)n0 * Dk + k0]),
                                 f2tf32(emb[(size_t)n0 * Dk + k0 + 4]),
                                 f2tf32(emb[(size_t)(n0 + 8) * Dk + k0]),
                                 f2tf32(emb[(size_t)(n0 + 8) * Dk + k0 + 4]));
            *reinterpret_cast<uint4*>(dst + (size_t)chunk * 4) = u;
        }
    }
}

// ---------------- main GEMM: 96x128 tile, 4 warps of 48x64, 3 CTAs/SM -------
// no smem; register-double-buffered LDG, prefetch-before-MMA (R6/R11 schedule).
// Wave-triples at the same SM slot take 3 consecutive tiles -> same nt -> B in L1.
__global__ void __launch_bounds__(128, 3)
gemm_main(const float* __restrict__ topic_b,
          const float* __restrict__ shared_b,
          float* __restrict__ out) {
    const int bid = blockIdx.x;
    const int w = bid / 148, s = bid % 148;
    int t;
    if (w < 36) {
        t = (w / 3) * 444 + s * 3 + (w % 3);     // triples share nt (mostly)
    } else {
        const int idx = 5328 + (w - 36) * 148 + s;
        if (idx >= NTILES) return;               // 140 no-op pad CTAs
        t = idx;
    }
    const int mt = ((t % MT96) + 42) % MT96;     // shared-heavy tiles (42,43) first
    const int nt = t / MT96;

    const int tid = threadIdx.x;
    const int wid = tid >> 5;
    const int lid = tid & 31;
    const int warp_m = wid >> 1;            // 0..1 (48-row band)
    const int warp_n = wid & 1;             // 0..1 (64-col band)
    const int g = lid >> 2;
    const int t4 = lid & 3;

    const int n0 = nt * 128;
    const int b_idx = n0 >> 10;
    const int l0 = n0 & (Ll - 1);

    float acc[3][8][4];                     // 96 regs
    #pragma unroll
    for (int mi = 0; mi < 3; ++mi)
        #pragma unroll
        for (int ni = 0; ni < 8; ++ni)
            #pragma unroll
            for (int r = 0; r < 4; ++r) acc[mi][ni][r] = 0.0f;

    // fragment pointers (float4 units):
    //   A step stride = 192 f4 (768 floats); j stride = 32 f4; j = warp_m*3 + mi
    //   B step stride = 256 f4; p stride = 32 f4
    const float4* pA = reinterpret_cast<const float4*>(
                           g_A + (size_t)mt * (KCH * A_CH)) + (warp_m * 3) * 32 + lid;
    const float4* pB = reinterpret_cast<const float4*>(
                           g_B + (size_t)nt * (KCH * B_CHUNK)) + warp_n * 128 + lid;

    float4 abuf[2][3], bbuf[2][4];
    #pragma unroll
    for (int mi = 0; mi < 3; ++mi) abuf[0][mi] = pA[mi * 32];
    #pragma unroll
    for (int p = 0; p < 4; ++p)    bbuf[0][p]  = pB[p * 32];
    pA += 192; pB += 256;

    #pragma unroll 4
    for (int s2 = 0; s2 < NSTEP; ++s2) {
        const int cur = s2 & 1, nxt = cur ^ 1;
        // prefetch step s2+1 BEFORE the MMA block (pad covers tail)
        #pragma unroll
        for (int mi = 0; mi < 3; ++mi) abuf[nxt][mi] = pA[mi * 32];
        #pragma unroll
        for (int p = 0; p < 4; ++p)    bbuf[nxt][p]  = pB[p * 32];
        pA += 192; pB += 256;

        #pragma unroll
        for (int mi = 0; mi < 3; ++mi) {
            const uint32_t* a = reinterpret_cast<const uint32_t*>(&abuf[cur][mi]);
            #pragma unroll
            for (int p = 0; p < 4; ++p) {
                const uint32_t* b = reinterpret_cast<const uint32_t*>(&bbuf[cur][p]);
                mma_tf32(acc[mi][2 * p], a, b);
                mma_tf32(acc[mi][2 * p + 1], a, b + 2);
            }
        }
    }

    // ---------------- epilogue: bias + direct stores (per 16-row block) -----
    #pragma unroll
    for (int mi = 0; mi < 3; ++mi) {
        const int f = mt * 96 + warp_m * 48 + mi * 16 + g;  // flat filter row
        if (f < 4096) {
            const int tt = f >> 7;          // topic
            const int fr = f & 127;         // channel within topic
            const float bia0 = topic_b[f];
            const float bia1 = topic_b[f + 8];
            const size_t base = ((size_t)(tt * Bb + b_idx) * 256 + fr) * Ll + l0;
            #pragma unroll
            for (int ni = 0; ni < 8; ++ni) {
                const int nn = warp_n * 64 + ni * 8 + 2 * t4;
                float2 v0 = make_float2(acc[mi][ni][0] + bia0, acc[mi][ni][1] + bia0);
                float2 v1 = make_float2(acc[mi][ni][2] + bia1, acc[mi][ni][3] + bia1);
                *reinterpret_cast<float2*>(out + base + nn) = v0;
                *reinterpret_cast<float2*>(out + base + 8 * Ll + nn) = v1;
            }
        } else {
            const int fr = f - 4096;        // shared channel
            const float bia0 = shared_b[fr];
            const float bia1 = shared_b[fr + 8];
            #pragma unroll
            for (int ni = 0; ni < 8; ++ni) {
                const int nn = warp_n * 64 + ni * 8 + 2 * t4;
                float2 v0 = make_float2(acc[mi][ni][0] + bia0, acc[mi][ni][1] + bia0);
                float2 v1 = make_float2(acc[mi][ni][2] + bia1, acc[mi][ni][3] + bia1);
                for (int tt = 0; tt < Tt; ++tt) {
                    const size_t base =
                        ((size_t)(tt * Bb + b_idx) * 256 + FT + fr) * Ll + l0;
                    *reinterpret_cast<float2*>(out + base + nn) = v0;
                    *reinterpret_cast<float2*>(out + base + 8 * Ll + nn) = v1;
                }
            }
        }
    }
}

// ---------------- launch ----------------
extern "C" void kernel_launch(void* const* d_in, const int* in_sizes, int n_in,
                              void* d_out, int out_size) {
    const float* emb      = (const float*)d_in[0];
    const float* topic_w  = (const float*)d_in[1];
    const float* topic_b  = (const float*)d_in[2];
    const float* shared_w = (const float*)d_in[3];
    const float* shared_b = (const float*)d_in[4];
    float* out            = (float*)d_out;

    prep_AB<<<dim3(MT96 + NT, KCH), 256>>>(topic_w, shared_w, emb);
    gemm_main<<<GRID_X, 128>>>(topic_b, shared_b, out);
}

// round 16
// speedup vs baseline: 1.1561x; 1.1561x over previous
#include <cuda_runtime.h>
#include <cstdint>

#define DEVINL static __device__ __forceinline__

// ---------------- problem constants ----------------
constexpr int Bb = 16, Ll = 1024, Dk = 512, Tt = 32, FT = 128;
constexpr int TM = 128, TN = 128, TK = 32;
constexpr int KCH = Dk / TK;                  // 16
constexpr int MT = 33, NT = 128;
constexpr int A_CHUNK = 4096;                 // floats per (mt,c)
constexpr int B_CHUNK = 4096;                 // floats per (nt,c)
constexpr int NSTEP = KCH * 4;                // 64 K-steps of 8
constexpr int NTILES = MT * NT;               // 4224
constexpr int GRID_X = 148 * 29;              // 4292 (68 no-op pad CTAs)

// fragment-ordered TF32 scratch (+2 chunk pad so tail prefetch stays in-bounds)
__device__ float g_A[(size_t)(MT * KCH + 2) * A_CHUNK];   // ~8.7 MB
__device__ float g_B[(size_t)(NT * KCH + 2) * B_CHUNK];   // ~33.6 MB

DEVINL uint32_t f2tf32(float f) {
    uint32_t r;
    asm("cvt.rna.tf32.f32 %0, %1;" : "=r"(r) : "f"(f));
    return r;
}

DEVINL void mma_tf32(float* d, const uint32_t* a, const uint32_t* b) {
    asm volatile(
        "mma.sync.aligned.m16n8k8.row.col.f32.tf32.tf32.f32 "
        "{%0,%1,%2,%3}, {%4,%5,%6,%7}, {%8,%9}, {%0,%1,%2,%3};"
        : "+f"(d[0]), "+f"(d[1]), "+f"(d[2]), "+f"(d[3])
        : "r"(a[0]), "r"(a[1]), "r"(a[2]), "r"(a[3]), "r"(b[0]), "r"(b[1]));
}

// ---------------- merged pre-pass: weights + embeddings -> fragment TF32 ----
// A inner = (((ks*2+wm)*4+mi)*32 + lane)*4 + r   (R11 layout)
// B inner = (((ks*2+wn)*4+p)*32 + lane)*4 + q    (R11 layout)
__global__ void prep_AB(const float* __restrict__ topic_w,
                        const float* __restrict__ shared_w,
                        const float* __restrict__ emb) {
    const int bx = blockIdx.x, c = blockIdx.y;
    const int tid = threadIdx.x;
    if (bx < MT) {
        const int mt = bx;
        const float* W = (mt == Tt) ? shared_w : (topic_w + (size_t)mt * FT * Dk);
        float* dst = g_A + (size_t)(mt * KCH + c) * A_CHUNK;
        #pragma unroll
        for (int i = 0; i < 4; ++i) {
            const int chunk = tid + 256 * i;          // 0..1023
            const int lane = chunk & 31;
            const int mi = (chunk >> 5) & 3;
            const int wm = (chunk >> 7) & 1;
            const int ks = chunk >> 8;                // 0..3
            const int g = lane >> 2, t4 = lane & 3;
            const int r0 = wm * 64 + mi * 16 + g;
            const int k0 = c * 32 + ks * 8 + t4;
            uint4 u = make_uint4(f2tf32(W[(size_t)r0 * Dk + k0]),
                                 f2tf32(W[(size_t)(r0 + 8) * Dk + k0]),
                                 f2tf32(W[(size_t)r0 * Dk + k0 + 4]),
                                 f2tf32(W[(size_t)(r0 + 8) * Dk + k0 + 4]));
            *reinterpret_cast<uint4*>(dst + (size_t)chunk * 4) = u;
        }
    } else {
        const int nt = bx - MT;
        float* dst = g_B + (size_t)(nt * KCH + c) * B_CHUNK;
        #pragma unroll
        for (int i = 0; i < 4; ++i) {
            const int chunk = tid + 256 * i;          // 0..1023
            const int lane = chunk & 31;
            const int p = (chunk >> 5) & 3;
            const int wn = (chunk >> 7) & 1;
            const int ks = chunk >> 8;                // 0..3
            const int g = lane >> 2, t4 = lane & 3;
            const int n0 = nt * TN + wn * 64 + (2 * p) * 8 + g;
            const int k0 = c * 32 + ks * 8 + t4;
            uint4 u = make_uint4(f2tf32(emb[(size_t)n0 * Dk + k0]),
                                 f2tf32(emb[(size_t)n0 * Dk + k0 + 4]),
                                 f2tf32(emb[(size_t)(n0 + 8) * Dk + k0]),
                                 f2tf32(emb[(size_t)(n0 + 8) * Dk + k0 + 4]));
            *reinterpret_cast<uint4*>(dst + (size_t)chunk * 4) = u;
        }
    }
}

// ---------------- main GEMM: 128x128 tile, 4 warps of 64x64, 2 CTAs/SM ------
// Champion config; prefetch split A-half / B-half around the MMA groups to
// halve the per-step L1tex LDG burst (cross-CTA queue contention).
__global__ void __launch_bounds__(128, 2)
gemm_main(const float* __restrict__ topic_b,
          const float* __restrict__ shared_b,
          float* __restrict__ out) {
    // ---- tile mapping: pair waves (2w, 2w+1) at same SM-slot onto adjacent t
    const int bid = blockIdx.x;
    const int w = bid / 148, s = bid % 148;
    int t;
    if (w < 28) {
        t = (w >> 1) * 296 + s * 2 + (w & 1);    // pairs share nt (97% of pairs)
    } else {
        if (s >= NTILES - 28 * 148) return;      // 80 tail tiles; rest no-op
        t = 28 * 148 + s;                        // 4144 + s
    }
    const int mt = t % MT;                       // 0..31 topics, 32 = shared
    const int nt = t / MT;                       // 0..127

    const int tid = threadIdx.x;
    const int wid = tid >> 5;
    const int lid = tid & 31;
    const int warp_m = wid >> 1;            // 0..1
    const int warp_n = wid & 1;             // 0..1
    const int g = lid >> 2;
    const int t4 = lid & 3;

    const bool is_shared = (mt == Tt);
    const float* bptr = is_shared ? shared_b : (topic_b + (size_t)mt * FT);
    const int n0 = nt * TN;
    const int b_idx = n0 >> 10;
    const int l0 = n0 & (Ll - 1);

    float acc[4][8][4];                     // 128 regs
    #pragma unroll
    for (int mi = 0; mi < 4; ++mi)
        #pragma unroll
        for (int ni = 0; ni < 8; ++ni)
            #pragma unroll
            for (int r = 0; r < 4; ++r) acc[mi][ni][r] = 0.0f;

    // per-step fragment pointers in float4 units:
    //   step stride = 256 f4 (1024 floats); mi/p stride = 32 f4
    const float4* pA = reinterpret_cast<const float4*>(
                           g_A + (size_t)mt * (KCH * A_CHUNK)) + warp_m * 128 + lid;
    const float4* pB = reinterpret_cast<const float4*>(
                           g_B + (size_t)nt * (KCH * B_CHUNK)) + warp_n * 128 + lid;

    float4 abuf[2][4], bbuf[2][4];
    #pragma unroll
    for (int mi = 0; mi < 4; ++mi) abuf[0][mi] = pA[mi * 32];
    #pragma unroll
    for (int p = 0; p < 4; ++p)    bbuf[0][p]  = pB[p * 32];
    pA += 256; pB += 256;

    #pragma unroll 4
    for (int s2 = 0; s2 < NSTEP; ++s2) {
        const int cur = s2 & 1, nxt = cur ^ 1;

        // first half of the prefetch burst: A for step s2+1
        #pragma unroll
        for (int mi = 0; mi < 4; ++mi) abuf[nxt][mi] = pA[mi * 32];
        pA += 256;

        // MMA groups mi = 0,1 on current step
        #pragma unroll
        for (int mi = 0; mi < 2; ++mi) {
            const uint32_t* a = reinterpret_cast<const uint32_t*>(&abuf[cur][mi]);
            #pragma unroll
            for (int p = 0; p < 4; ++p) {
                const uint32_t* b = reinterpret_cast<const uint32_t*>(&bbuf[cur][p]);
                mma_tf32(acc[mi][2 * p], a, b);
                mma_tf32(acc[mi][2 * p + 1], a, b + 2);
            }
        }

        // second half of the prefetch burst: B for step s2+1
        #pragma unroll
        for (int p = 0; p < 4; ++p) bbuf[nxt][p] = pB[p * 32];
        pB += 256;

        // MMA groups mi = 2,3 on current step
        #pragma unroll
        for (int mi = 2; mi < 4; ++mi) {
            const uint32_t* a = reinterpret_cast<const uint32_t*>(&abuf[cur][mi]);
            #pragma unroll
            for (int p = 0; p < 4; ++p) {
                const uint32_t* b = reinterpret_cast<const uint32_t*>(&bbuf[cur][p]);
                mma_tf32(acc[mi][2 * p], a, b);
                mma_tf32(acc[mi][2 * p + 1], a, b + 2);
            }
        }
    }

    // ---------------- epilogue: bias + direct stores ----------------
    if (!is_shared) {
        const size_t base = ((size_t)(mt * Bb + b_idx) * 256) * Ll + l0;
        #pragma unroll
        for (int mi = 0; mi < 4; ++mi) {
            const int m0 = warp_m * 64 + mi * 16 + g;
            const float bia0 = bptr[m0];
            const float bia1 = bptr[m0 + 8];
            #pragma unroll
            for (int ni = 0; ni < 8; ++ni) {
                const int nn = warp_n * 64 + ni * 8 + 2 * t4;
                float2 v0 = make_float2(acc[mi][ni][0] + bia0, acc[mi][ni][1] + bia0);
                float2 v1 = make_float2(acc[mi][ni][2] + bia1, acc[mi][ni][3] + bia1);
                *reinterpret_cast<float2*>(out + base + (size_t)m0 * Ll + nn) = v0;
                *reinterpret_cast<float2*>(out + base + (size_t)(m0 + 8) * Ll + nn) = v1;
            }
        }
    } else {
        #pragma unroll
        for (int mi = 0; mi < 4; ++mi) {
            const int m0 = warp_m * 64 + mi * 16 + g;
            const float bia0 = bptr[m0];
            const float bia1 = bptr[m0 + 8];
            #pragma unroll
            for (int ni = 0; ni < 8; ++ni) {
                const int nn = warp_n * 64 + ni * 8 + 2 * t4;
                float2 v0 = make_float2(acc[mi][ni][0] + bia0, acc[mi][ni][1] + bia0);
                float2 v1 = make_float2(acc[mi][ni][2] + bia1, acc[mi][ni][3] + bia1);
                for (int tt = 0; tt < Tt; ++tt) {
                    const size_t base =
                        ((size_t)(tt * Bb + b_idx) * 256 + FT) * Ll + l0;
                    *reinterpret_cast<float2*>(out + base + (size_t)m0 * Ll + nn) = v0;
                    *reinterpret_cast<float2*>(out + base + (size_t)(m0 + 8) * Ll + nn) = v1;
                }
            }
        }
    }
}

// ---------------- launch ----------------
extern "C" void kernel_launch(void* const* d_in, const int* in_sizes, int n_in,
                              void* d_out, int out_size) {
    const float* emb      = (const float*)d_in[0];
    const float* topic_w  = (const float*)d_in[1];
    const float* topic_b  = (const float*)d_in[2];
    const float* shared_w = (const float*)d_in[3];
    const float* shared_b = (const float*)d_in[4];
    float* out            = (float*)d_out;

    prep_AB<<<dim3(MT + NT, KCH), 256>>>(topic_w, shared_w, emb);
    gemm_main<<<GRID_X, 128>>>(topic_b, shared_b, out);
}

// round 17
// speedup vs baseline: 1.1583x; 1.0019x over previous
#include <cuda_runtime.h>
#include <cstdint>

#define DEVINL static __device__ __forceinline__

// ---------------- problem constants ----------------
constexpr int Bb = 16, Ll = 1024, Dk = 512, Tt = 32, FT = 128;
constexpr int TM = 128, TN = 128, TK = 32;
constexpr int KCH = Dk / TK;                  // 16
constexpr int MT = 33, NT = 128;
constexpr int A_CHUNK = 4096;                 // floats per (mt,c)
constexpr int B_CHUNK = 4096;                 // floats per (nt,c)
constexpr int NSTEP = KCH * 4;                // 64 K-steps of 8
constexpr int NTILES = MT * NT;               // 4224
constexpr int GRID_X = 148 * 29;              // 4292 (68 no-op pad CTAs)

// fragment-ordered TF32 scratch (+2 chunk pad so tail prefetch stays in-bounds)
__device__ float g_A[(size_t)(MT * KCH + 2) * A_CHUNK];   // ~8.7 MB
__device__ float g_B[(size_t)(NT * KCH + 2) * B_CHUNK];   // ~33.6 MB

DEVINL uint32_t f2tf32(float f) {
    uint32_t r;
    asm("cvt.rna.tf32.f32 %0, %1;" : "=r"(r) : "f"(f));
    return r;
}

DEVINL void mma_tf32(float* d, const uint32_t* a, const uint32_t* b) {
    asm volatile(
        "mma.sync.aligned.m16n8k8.row.col.f32.tf32.tf32.f32 "
        "{%0,%1,%2,%3}, {%4,%5,%6,%7}, {%8,%9}, {%0,%1,%2,%3};"
        : "+f"(d[0]), "+f"(d[1]), "+f"(d[2]), "+f"(d[3])
        : "r"(a[0]), "r"(a[1]), "r"(a[2]), "r"(a[3]), "r"(b[0]), "r"(b[1]));
}

// ---------------- merged pre-pass: weights + embeddings -> fragment TF32 ----
// A inner = (((ks*2+wm)*4+mi)*32 + lane)*4 + r   (R11 layout)
// B inner = (((ks*2+wn)*4+p)*32 + lane)*4 + q    (R11 layout)
__global__ void prep_AB(const float* __restrict__ topic_w,
                        const float* __restrict__ shared_w,
                        const float* __restrict__ emb) {
    const int bx = blockIdx.x, c = blockIdx.y;
    const int tid = threadIdx.x;
    if (bx < MT) {
        const int mt = bx;
        const float* W = (mt == Tt) ? shared_w : (topic_w + (size_t)mt * FT * Dk);
        float* dst = g_A + (size_t)(mt * KCH + c) * A_CHUNK;
        #pragma unroll
        for (int i = 0; i < 4; ++i) {
            const int chunk = tid + 256 * i;          // 0..1023
            const int lane = chunk & 31;
            const int mi = (chunk >> 5) & 3;
            const int wm = (chunk >> 7) & 1;
            const int ks = chunk >> 8;                // 0..3
            const int g = lane >> 2, t4 = lane & 3;
            const int r0 = wm * 64 + mi * 16 + g;
            const int k0 = c * 32 + ks * 8 + t4;
            uint4 u = make_uint4(f2tf32(W[(size_t)r0 * Dk + k0]),
                                 f2tf32(W[(size_t)(r0 + 8) * Dk + k0]),
                                 f2tf32(W[(size_t)r0 * Dk + k0 + 4]),
                                 f2tf32(W[(size_t)(r0 + 8) * Dk + k0 + 4]));
            *reinterpret_cast<uint4*>(dst + (size_t)chunk * 4) = u;
        }
    } else {
        const int nt = bx - MT;
        float* dst = g_B + (size_t)(nt * KCH + c) * B_CHUNK;
        #pragma unroll
        for (int i = 0; i < 4; ++i) {
            const int chunk = tid + 256 * i;          // 0..1023
            const int lane = chunk & 31;
            const int p = (chunk >> 5) & 3;
            const int wn = (chunk >> 7) & 1;
            const int ks = chunk >> 8;                // 0..3
            const int g = lane >> 2, t4 = lane & 3;
            const int n0 = nt * TN + wn * 64 + (2 * p) * 8 + g;
            const int k0 = c * 32 + ks * 8 + t4;
            uint4 u = make_uint4(f2tf32(emb[(size_t)n0 * Dk + k0]),
                                 f2tf32(emb[(size_t)n0 * Dk + k0 + 4]),
                                 f2tf32(emb[(size_t)(n0 + 8) * Dk + k0]),
                                 f2tf32(emb[(size_t)(n0 + 8) * Dk + k0 + 4]));
            *reinterpret_cast<uint4*>(dst + (size_t)chunk * 4) = u;
        }
    }
}

// ---------------- main GEMM: 128x128 tile, 4 warps of 64x64, 2 CTAs/SM ------
// R16 champion; only change: mainloop unroll 4 -> 8 (wider ptxas scheduling
// window so next-iteration LDG bursts can hoist above trailing MMA groups).
__global__ void __launch_bounds__(128, 2)
gemm_main(const float* __restrict__ topic_b,
          const float* __restrict__ shared_b,
          float* __restrict__ out) {
    // ---- tile mapping: pair waves (2w, 2w+1) at same SM-slot onto adjacent t
    const int bid = blockIdx.x;
    const int w = bid / 148, s = bid % 148;
    int t;
    if (w < 28) {
        t = (w >> 1) * 296 + s * 2 + (w & 1);    // pairs share nt (97% of pairs)
    } else {
        if (s >= NTILES - 28 * 148) return;      // 80 tail tiles; rest no-op
        t = 28 * 148 + s;                        // 4144 + s
    }
    const int mt = t % MT;                       // 0..31 topics, 32 = shared
    const int nt = t / MT;                       // 0..127

    const int tid = threadIdx.x;
    const int wid = tid >> 5;
    const int lid = tid & 31;
    const int warp_m = wid >> 1;            // 0..1
    const int warp_n = wid & 1;             // 0..1
    const int g = lid >> 2;
    const int t4 = lid & 3;

    const bool is_shared = (mt == Tt);
    const float* bptr = is_shared ? shared_b : (topic_b + (size_t)mt * FT);
    const int n0 = nt * TN;
    const int b_idx = n0 >> 10;
    const int l0 = n0 & (Ll - 1);

    float acc[4][8][4];                     // 128 regs
    #pragma unroll
    for (int mi = 0; mi < 4; ++mi)
        #pragma unroll
        for (int ni = 0; ni < 8; ++ni)
            #pragma unroll
            for (int r = 0; r < 4; ++r) acc[mi][ni][r] = 0.0f;

    // per-step fragment pointers in float4 units:
    //   step stride = 256 f4 (1024 floats); mi/p stride = 32 f4
    const float4* pA = reinterpret_cast<const float4*>(
                           g_A + (size_t)mt * (KCH * A_CHUNK)) + warp_m * 128 + lid;
    const float4* pB = reinterpret_cast<const float4*>(
                           g_B + (size_t)nt * (KCH * B_CHUNK)) + warp_n * 128 + lid;

    float4 abuf[2][4], bbuf[2][4];
    #pragma unroll
    for (int mi = 0; mi < 4; ++mi) abuf[0][mi] = pA[mi * 32];
    #pragma unroll
    for (int p = 0; p < 4; ++p)    bbuf[0][p]  = pB[p * 32];
    pA += 256; pB += 256;

    #pragma unroll 8
    for (int s2 = 0; s2 < NSTEP; ++s2) {
        const int cur = s2 & 1, nxt = cur ^ 1;

        // first half of the prefetch burst: A for step s2+1
        #pragma unroll
        for (int mi = 0; mi < 4; ++mi) abuf[nxt][mi] = pA[mi * 32];
        pA += 256;

        // MMA groups mi = 0,1 on current step
        #pragma unroll
        for (int mi = 0; mi < 2; ++mi) {
            const uint32_t* a = reinterpret_cast<const uint32_t*>(&abuf[cur][mi]);
            #pragma unroll
            for (int p = 0; p < 4; ++p) {
                const uint32_t* b = reinterpret_cast<const uint32_t*>(&bbuf[cur][p]);
                mma_tf32(acc[mi][2 * p], a, b);
                mma_tf32(acc[mi][2 * p + 1], a, b + 2);
            }
        }

        // second half of the prefetch burst: B for step s2+1
        #pragma unroll
        for (int p = 0; p < 4; ++p) bbuf[nxt][p] = pB[p * 32];
        pB += 256;

        // MMA groups mi = 2,3 on current step
        #pragma unroll
        for (int mi = 2; mi < 4; ++mi) {
            const uint32_t* a = reinterpret_cast<const uint32_t*>(&abuf[cur][mi]);
            #pragma unroll
            for (int p = 0; p < 4; ++p) {
                const uint32_t* b = reinterpret_cast<const uint32_t*>(&bbuf[cur][p]);
                mma_tf32(acc[mi][2 * p], a, b);
                mma_tf32(acc[mi][2 * p + 1], a, b + 2);
            }
        }
    }

    // ---------------- epilogue: bias + direct stores ----------------
    if (!is_shared) {
        const size_t base = ((size_t)(mt * Bb + b_idx) * 256) * Ll + l0;
        #pragma unroll
        for (int mi = 0; mi < 4; ++mi) {
            const int m0 = warp_m * 64 + mi * 16 + g;
            const float bia0 = bptr[m0];
            const float bia1 = bptr[m0 + 8];
            #pragma unroll
            for (int ni = 0; ni < 8; ++ni) {
                const int nn = warp_n * 64 + ni * 8 + 2 * t4;
                float2 v0 = make_float2(acc[mi][ni][0] + bia0, acc[mi][ni][1] + bia0);
                float2 v1 = make_float2(acc[mi][ni][2] + bia1, acc[mi][ni][3] + bia1);
                *reinterpret_cast<float2*>(out + base + (size_t)m0 * Ll + nn) = v0;
                *reinterpret_cast<float2*>(out + base + (size_t)(m0 + 8) * Ll + nn) = v1;
            }
        }
    } else {
        #pragma unroll
        for (int mi = 0; mi < 4; ++mi) {
            const int m0 = warp_m * 64 + mi * 16 + g;
            const float bia0 = bptr[m0];
            const float bia1 = bptr[m0 + 8];
            #pragma unroll
            for (int ni = 0; ni < 8; ++ni) {
                const int nn = warp_n * 64 + ni * 8 + 2 * t4;
                float2 v0 = make_float2(acc[mi][ni][0] + bia0, acc[mi][ni][1] + bia0);
                float2 v1 = make_float2(acc[mi][ni][2] + bia1, acc[mi][ni][3] + bia1);
                for (int tt = 0; tt < Tt; ++tt) {
                    const size_t base =
                        ((size_t)(tt * Bb + b_idx) * 256 + FT) * Ll + l0;
                    *reinterpret_cast<float2*>(out + base + (size_t)m0 * Ll + nn) = v0;
                    *reinterpret_cast<float2*>(out + base + (size_t)(m0 + 8) * Ll + nn) = v1;
                }
            }
        }
    }
}

// ---------------- launch ----------------
extern "C" void kernel_launch(void* const* d_in, const int* in_sizes, int n_in,
                              void* d_out, int out_size) {
    const float* emb      = (const float*)d_in[0];
    const float* topic_w  = (const float*)d_in[1];
    const float* topic_b  = (const float*)d_in[2];
    const float* shared_w = (const float*)d_in[3];
    const float* shared_b = (const float*)d_in[4];
    float* out            = (float*)d_out;

    prep_AB<<<dim3(MT + NT, KCH), 256>>>(topic_w, shared_w, emb);
    gemm_main<<<GRID_X, 128>>>(topic_b, shared_b, out);
}